// round 14
// baseline (speedup 1.0000x reference)
#include <cuda_runtime.h>
#include <cuda_fp16.h>
#include <mma.h>
#include <cstdint>

using namespace nvcuda;

// ---------------------------------------------------------------------------
// GCN: out = L3(relu(L2(relu(L1(x)))))   symmetric norm + self loops.
// Tensor-core GEMM (wmma fp16 x fp16 -> fp32) with dinv[row] scaling moved
// INTO the prologue ((x@W)*d = (d*x)@W), so the accumulator is converted
// elementwise to fp16 and stored straight to global msg via store_matrix_sync
// (no fp32 smem staging, 27.6 KB smem, 1 sync). msg + agg fp16.
// Layer 1 GEMM unscaled (fork-safe vs CSR build); gather-1 applies dinv[src].
// Final gather fused with b3/dinv epilogue into d_out (fp32).
// ---------------------------------------------------------------------------

static constexpr int NMAX = 100000;
static constexpr int NPAD = ((NMAX + 127) / 128) * 128;   // 100096
static constexpr int D    = 64;
static constexpr int CAP  = 96;

__device__ float g_dinv [NMAX];
__device__ int   g_count[NMAX];
__device__ int   g_csrc [NMAX * CAP];
__device__ uint4 g_msg  [NPAD * 8];        // fp16, padded for full-tile stores
__device__ uint4 g_aggA [NMAX * 8];        // fp16 agg ping
__device__ uint4 g_aggB [NMAX * 8];        // fp16 agg pong

// ---------------------------------------------------------------------------
// CSR build
// ---------------------------------------------------------------------------
__global__ void k_zero(int N) {
    int i = blockIdx.x * blockDim.x + threadIdx.x;
    if (i < N) g_count[i] = 0;
}

__global__ void k_fill(const int* __restrict__ src, const int* __restrict__ dst,
                       int E) {
    int e = blockIdx.x * blockDim.x + threadIdx.x;
    if (e >= E) return;
    int s = __ldg(src + e);
    int d = __ldg(dst + e);
    int pos = atomicAdd(&g_count[d], 1);
    if (pos < CAP) g_csrc[d * CAP + pos] = s;
}

__global__ void k_dinv(int N) {
    int i = blockIdx.x * blockDim.x + threadIdx.x;
    if (i < N) g_dinv[i] = rsqrtf((float)g_count[i] + 1.0f);
}

// ---------------------------------------------------------------------------
// fp16 helpers
// ---------------------------------------------------------------------------
struct F8 { float v[8]; };

__device__ __forceinline__ F8 unpack8(uint4 u) {
    F8 r;
    float2 f0 = __half22float2(*reinterpret_cast<__half2*>(&u.x));
    float2 f1 = __half22float2(*reinterpret_cast<__half2*>(&u.y));
    float2 f2 = __half22float2(*reinterpret_cast<__half2*>(&u.z));
    float2 f3 = __half22float2(*reinterpret_cast<__half2*>(&u.w));
    r.v[0] = f0.x; r.v[1] = f0.y; r.v[2] = f1.x; r.v[3] = f1.y;
    r.v[4] = f2.x; r.v[5] = f2.y; r.v[6] = f3.x; r.v[7] = f3.y;
    return r;
}

__device__ __forceinline__ uint4 pack8(const F8& a) {
    __half2 h0 = __floats2half2_rn(a.v[0], a.v[1]);
    __half2 h1 = __floats2half2_rn(a.v[2], a.v[3]);
    __half2 h2 = __floats2half2_rn(a.v[4], a.v[5]);
    __half2 h3 = __floats2half2_rn(a.v[6], a.v[7]);
    uint4 u;
    u.x = *reinterpret_cast<uint32_t*>(&h0);
    u.y = *reinterpret_cast<uint32_t*>(&h1);
    u.z = *reinterpret_cast<uint32_t*>(&h2);
    u.w = *reinterpret_cast<uint32_t*>(&h3);
    return u;
}

// ---------------------------------------------------------------------------
// Gather core: 8 threads per node, each covers 8 halfs (16 B). fp32 accum.
// ---------------------------------------------------------------------------
template <bool SCALE_SRC>
__device__ __forceinline__ F8 gather_node(int node, int c)
{
    int cnt = g_count[node];
    if (cnt > CAP) cnt = CAP;
    const int* lst = g_csrc + (size_t)node * CAP;

    F8 acc = unpack8(g_msg[(size_t)node * 8 + c]);   // self loop
    if (SCALE_SRC) {
        float dn = g_dinv[node];
        #pragma unroll
        for (int j = 0; j < 8; j++) acc.v[j] *= dn;
    }

    int i = 0;
    for (; i + 4 <= cnt; i += 4) {
        int s0 = __ldg(lst + i);
        int s1 = __ldg(lst + i + 1);
        int s2 = __ldg(lst + i + 2);
        int s3 = __ldg(lst + i + 3);
        F8 a = unpack8(g_msg[(size_t)s0 * 8 + c]);
        F8 b = unpack8(g_msg[(size_t)s1 * 8 + c]);
        F8 cc = unpack8(g_msg[(size_t)s2 * 8 + c]);
        F8 dd = unpack8(g_msg[(size_t)s3 * 8 + c]);
        if (SCALE_SRC) {
            float w0 = g_dinv[s0], w1 = g_dinv[s1];
            float w2 = g_dinv[s2], w3 = g_dinv[s3];
            #pragma unroll
            for (int j = 0; j < 8; j++) {
                acc.v[j] = fmaf(a.v[j], w0, acc.v[j]);
                acc.v[j] = fmaf(b.v[j], w1, acc.v[j]);
                acc.v[j] = fmaf(cc.v[j], w2, acc.v[j]);
                acc.v[j] = fmaf(dd.v[j], w3, acc.v[j]);
            }
        } else {
            #pragma unroll
            for (int j = 0; j < 8; j++)
                acc.v[j] += (a.v[j] + b.v[j]) + (cc.v[j] + dd.v[j]);
        }
    }
    for (; i < cnt; i++) {
        int s0 = __ldg(lst + i);
        F8 a = unpack8(g_msg[(size_t)s0 * 8 + c]);
        if (SCALE_SRC) {
            float w0 = g_dinv[s0];
            #pragma unroll
            for (int j = 0; j < 8; j++) acc.v[j] = fmaf(a.v[j], w0, acc.v[j]);
        } else {
            #pragma unroll
            for (int j = 0; j < 8; j++) acc.v[j] += a.v[j];
        }
    }
    return acc;
}

// ---------------------------------------------------------------------------
// Tensor-core GEMM: 128-row tile, 256 threads (8 warps), warp w = 16 rows.
// Prologue applies relu(agg*dinv+b) AND the output dinv[row] scale; MMA;
// fp32 accum fragment converted elementwise to fp16 and stored DIRECTLY to
// global g_msg (ldm=64). smem: x[128x72] + W[64x72] fp16 = 27.6 KB; 1 sync.
// ---------------------------------------------------------------------------
static constexpr int XLD = 72;   // fp16 leading dim (mult of 8)

__global__ void __launch_bounds__(256, 6)
k_gemm(const float* __restrict__ xin_ext,   // non-null for layer 1
       int in_buf,                          // fp16 agg buffer (internal)
       const float* __restrict__ W,
       const float* __restrict__ b_prev,    // prev-layer bias (internal)
       int N)
{
    __shared__ __align__(16) __half xs[128 * XLD];
    __shared__ __align__(16) __half Ws[64 * XLD];

    const int tid  = threadIdx.x;
    const int wid  = tid >> 5;
    const int row0 = blockIdx.x * 128;

    // Load + convert W: 1024 float4, 4 per thread.
    {
        const float4* W4 = (const float4*)W;
        #pragma unroll
        for (int i = 0; i < 4; i++) {
            int j   = tid + i * 256;        // float4 index 0..1023
            int row = j >> 4;               // W row (k)
            int c4  = j & 15;               // float4 col group
            float4 v = W4[j];
            __half2 h0 = __floats2half2_rn(v.x, v.y);
            __half2 h1 = __floats2half2_rn(v.z, v.w);
            uint2 u;
            u.x = *reinterpret_cast<uint32_t*>(&h0);
            u.y = *reinterpret_cast<uint32_t*>(&h1);
            *reinterpret_cast<uint2*>(Ws + row * XLD + c4 * 4) = u;
        }
    }

    // Prologue: build fp16 x' tile (output row-scale folded in).
    if (xin_ext) {
        // Layer 1: raw fp32 node_embed, unscaled (fork-safe: no dinv read).
        #pragma unroll
        for (int it = 0; it < 8; it++) {
            int j   = tid + it * 256;       // 0..2047
            int r   = j >> 4;
            int c4  = j & 15;
            int row = row0 + r;
            float4 v = make_float4(0.f, 0.f, 0.f, 0.f);
            if (row < N)
                v = ((const float4*)xin_ext)[(size_t)row * 16 + c4];
            __half2 h0 = __floats2half2_rn(v.x, v.y);
            __half2 h1 = __floats2half2_rn(v.z, v.w);
            uint2 u;
            u.x = *reinterpret_cast<uint32_t*>(&h0);
            u.y = *reinterpret_cast<uint32_t*>(&h1);
            *reinterpret_cast<uint2*>(xs + r * XLD + c4 * 4) = u;
        }
    } else {
        // Internal: x' = dinv[row] * relu(agg*dinv[row] + b_prev).
        const uint4* agg4 = in_buf ? g_aggB : g_aggA;
        #pragma unroll
        for (int it = 0; it < 4; it++) {
            int j   = tid + it * 256;       // 0..1023
            int r   = j >> 3;
            int c   = j & 7;                // uint4 group (8 halfs)
            int row = row0 + r;
            F8 o;
            #pragma unroll
            for (int q = 0; q < 8; q++) o.v[q] = 0.f;
            if (row < N) {
                F8 a = unpack8(agg4[(size_t)row * 8 + c]);
                float s  = g_dinv[row];
                float4 b0 = ((const float4*)b_prev)[c * 2];
                float4 b1 = ((const float4*)b_prev)[c * 2 + 1];
                float bb[8] = {b0.x, b0.y, b0.z, b0.w, b1.x, b1.y, b1.z, b1.w};
                #pragma unroll
                for (int q = 0; q < 8; q++)
                    o.v[q] = s * fmaxf(fmaf(a.v[q], s, bb[q]), 0.f);
            }
            *reinterpret_cast<uint4*>(xs + r * XLD + c * 8) = pack8(o);
        }
    }
    __syncthreads();

    // MMA: 4 k-steps x 4 n-tiles of 16x16x16, fp32 accumulate.
    wmma::fragment<wmma::accumulator, 16, 16, 16, float> acc[4];
    #pragma unroll
    for (int n = 0; n < 4; n++) wmma::fill_fragment(acc[n], 0.0f);

    #pragma unroll
    for (int ks = 0; ks < 4; ks++) {
        wmma::fragment<wmma::matrix_a, 16, 16, 16, __half, wmma::row_major> fa;
        wmma::load_matrix_sync(fa, xs + (wid * 16) * XLD + ks * 16, XLD);
        #pragma unroll
        for (int n = 0; n < 4; n++) {
            wmma::fragment<wmma::matrix_b, 16, 16, 16, __half, wmma::row_major> fb;
            wmma::load_matrix_sync(fb, Ws + (ks * 16) * XLD + n * 16, XLD);
            wmma::mma_sync(acc[n], fa, fb, acc[n]);
        }
    }

    // Convert fp32 accum -> fp16 elementwise, store straight to global msg.
    // (msg buffer padded to NPAD rows so full-tile stores are in-bounds.)
    __half* msg = (__half*)g_msg;
    #pragma unroll
    for (int n = 0; n < 4; n++) {
        wmma::fragment<wmma::accumulator, 16, 16, 16, __half> hacc;
        #pragma unroll
        for (int i = 0; i < hacc.num_elements; i++)
            hacc.x[i] = __float2half(acc[n].x[i]);
        wmma::store_matrix_sync(
            msg + (size_t)(row0 + wid * 16) * 64 + n * 16, hacc, 64,
            wmma::mem_row_major);
    }
}

// ---------------------------------------------------------------------------
// Gather kernels: 8 threads per node; agg stored fp16.
// ---------------------------------------------------------------------------
template <bool SCALE_SRC>
__global__ void __launch_bounds__(256)
k_gather(int out_buf, int N)
{
    int t = blockIdx.x * blockDim.x + threadIdx.x;
    if (t >= N * 8) return;
    int node = t >> 3;
    int c    = t & 7;
    F8 acc = gather_node<SCALE_SRC>(node, c);
    uint4* agg = out_buf ? g_aggB : g_aggA;
    agg[(size_t)node * 8 + c] = pack8(acc);
}

// Final: out = gather(msg)*dinv + b3  (fp32 out; msg already row-scaled)
__global__ void __launch_bounds__(256)
k_out(float* __restrict__ out, const float* __restrict__ b3, int N)
{
    int t = blockIdx.x * blockDim.x + threadIdx.x;
    if (t >= N * 8) return;
    int node = t >> 3;
    int c    = t & 7;
    F8 acc = gather_node<false>(node, c);
    float s = g_dinv[node];
    float4 b0 = ((const float4*)b3)[c * 2];
    float4 b1 = ((const float4*)b3)[c * 2 + 1];
    float4 o0 = make_float4(fmaf(acc.v[0], s, b0.x), fmaf(acc.v[1], s, b0.y),
                            fmaf(acc.v[2], s, b0.z), fmaf(acc.v[3], s, b0.w));
    float4 o1 = make_float4(fmaf(acc.v[4], s, b1.x), fmaf(acc.v[5], s, b1.y),
                            fmaf(acc.v[6], s, b1.z), fmaf(acc.v[7], s, b1.w));
    float4* dst = (float4*)(out + (size_t)node * 64 + c * 8);
    dst[0] = o0;
    dst[1] = o1;
}

// ---------------------------------------------------------------------------
// Launch. Stream/events created per call (host objects only, no device mem).
// ---------------------------------------------------------------------------
extern "C" void kernel_launch(void* const* d_in, const int* in_sizes, int n_in,
                              void* d_out, int out_size)
{
    const float* node_embed = (const float*)d_in[0];
    const int*   edges      = (const int*)d_in[1];
    const float* W1 = (const float*)d_in[2];
    const float* b1 = (const float*)d_in[3];
    const float* W2 = (const float*)d_in[4];
    const float* b2 = (const float*)d_in[5];
    const float* W3 = (const float*)d_in[6];
    const float* b3 = (const float*)d_in[7];
    float* out = (float*)d_out;

    const int N = in_sizes[0] / D;
    const int E = in_sizes[1] / 2;
    const int* src = edges;
    const int* dst = edges + E;

    const int TB = 256;
    const int gemm_blocks   = (N + 127) / 128;
    const int gather_blocks = (N * 8 + TB - 1) / TB;

    cudaStream_t s2 = nullptr;
    cudaEvent_t evFork = nullptr, evJoin = nullptr;
    bool fork_ok =
        cudaStreamCreateWithFlags(&s2, cudaStreamNonBlocking) == cudaSuccess &&
        cudaEventCreateWithFlags(&evFork, cudaEventDisableTiming) == cudaSuccess &&
        cudaEventCreateWithFlags(&evJoin, cudaEventDisableTiming) == cudaSuccess;

    if (fork_ok) {
        // Fork: CSR build (count/csrc/dinv) || layer-1 GEMM (msg only).
        cudaEventRecord(evFork, 0);
        cudaStreamWaitEvent(s2, evFork, 0);

        k_zero<<<(N + TB - 1) / TB, TB>>>(N);
        k_fill<<<(E + TB - 1) / TB, TB>>>(src, dst, E);
        k_dinv<<<(N + TB - 1) / TB, TB>>>(N);

        k_gemm<<<gemm_blocks, TB, 0, s2>>>(node_embed, 0, W1, nullptr, N);

        cudaEventRecord(evJoin, s2);
        cudaStreamWaitEvent(0, evJoin, 0);
    } else {
        k_zero<<<(N + TB - 1) / TB, TB>>>(N);
        k_fill<<<(E + TB - 1) / TB, TB>>>(src, dst, E);
        k_dinv<<<(N + TB - 1) / TB, TB>>>(N);
        k_gemm<<<gemm_blocks, TB>>>(node_embed, 0, W1, nullptr, N);
    }

    // Layer 1 aggregate (applies dinv[src]) -> A (fp16)
    k_gather<true><<<gather_blocks, TB>>>(0, N);

    // Layer 2: x' = dinv*relu(A*dinv + b1) -> msg; gather -> B (fp16)
    k_gemm<<<gemm_blocks, TB>>>(nullptr, 0, W2, b1, N);
    k_gather<false><<<gather_blocks, TB>>>(1, N);

    // Layer 3: x' = dinv*relu(B*dinv + b2) -> msg; fused gather -> out
    k_gemm<<<gemm_blocks, TB>>>(nullptr, 1, W3, b2, N);
    k_out<<<gather_blocks, TB>>>(out, b3, N);

    // s2/events intentionally not destroyed (unsafe mid-capture; host-only).
}

// round 15
// speedup vs baseline: 1.0187x; 1.0187x over previous
#include <cuda_runtime.h>
#include <cuda_fp16.h>
#include <mma.h>
#include <cstdint>

using namespace nvcuda;

// ---------------------------------------------------------------------------
// GCN: out = L3(relu(L2(relu(L1(x)))))   symmetric norm + self loops.
// Tensor-core GEMM (wmma fp16 x fp16 -> fp32). dinv[row] output scale folded
// into the prologue ((x@W)*d = (d*x)@W). Epilogue: half fragments staged in
// smem (reusing the x tile region), then coalesced uint4 writes to g_msg.
// msg + agg fp16; gathers accumulate fp32.
// Layer 1 GEMM unscaled (fork-safe vs CSR build); gather-1 applies dinv[src].
// Final gather fused with b3/dinv epilogue into d_out (fp32).
// ---------------------------------------------------------------------------

static constexpr int NMAX = 100000;
static constexpr int D    = 64;
static constexpr int CAP  = 96;

__device__ float g_dinv [NMAX];
__device__ int   g_count[NMAX];
__device__ int   g_csrc [NMAX * CAP];
__device__ uint4 g_msg  [NMAX * 8];        // fp16: 64 halfs/row
__device__ uint4 g_aggA [NMAX * 8];        // fp16 agg ping
__device__ uint4 g_aggB [NMAX * 8];        // fp16 agg pong

// ---------------------------------------------------------------------------
// CSR build
// ---------------------------------------------------------------------------
__global__ void k_zero(int N) {
    int i = blockIdx.x * blockDim.x + threadIdx.x;
    if (i < N) g_count[i] = 0;
}

__global__ void k_fill(const int* __restrict__ src, const int* __restrict__ dst,
                       int E) {
    int e = blockIdx.x * blockDim.x + threadIdx.x;
    if (e >= E) return;
    int s = __ldg(src + e);
    int d = __ldg(dst + e);
    int pos = atomicAdd(&g_count[d], 1);
    if (pos < CAP) g_csrc[d * CAP + pos] = s;
}

__global__ void k_dinv(int N) {
    int i = blockIdx.x * blockDim.x + threadIdx.x;
    if (i < N) g_dinv[i] = rsqrtf((float)g_count[i] + 1.0f);
}

// ---------------------------------------------------------------------------
// fp16 helpers
// ---------------------------------------------------------------------------
struct F8 { float v[8]; };

__device__ __forceinline__ F8 unpack8(uint4 u) {
    F8 r;
    float2 f0 = __half22float2(*reinterpret_cast<__half2*>(&u.x));
    float2 f1 = __half22float2(*reinterpret_cast<__half2*>(&u.y));
    float2 f2 = __half22float2(*reinterpret_cast<__half2*>(&u.z));
    float2 f3 = __half22float2(*reinterpret_cast<__half2*>(&u.w));
    r.v[0] = f0.x; r.v[1] = f0.y; r.v[2] = f1.x; r.v[3] = f1.y;
    r.v[4] = f2.x; r.v[5] = f2.y; r.v[6] = f3.x; r.v[7] = f3.y;
    return r;
}

__device__ __forceinline__ uint4 pack8(const F8& a) {
    __half2 h0 = __floats2half2_rn(a.v[0], a.v[1]);
    __half2 h1 = __floats2half2_rn(a.v[2], a.v[3]);
    __half2 h2 = __floats2half2_rn(a.v[4], a.v[5]);
    __half2 h3 = __floats2half2_rn(a.v[6], a.v[7]);
    uint4 u;
    u.x = *reinterpret_cast<uint32_t*>(&h0);
    u.y = *reinterpret_cast<uint32_t*>(&h1);
    u.z = *reinterpret_cast<uint32_t*>(&h2);
    u.w = *reinterpret_cast<uint32_t*>(&h3);
    return u;
}

// ---------------------------------------------------------------------------
// Gather core: 8 threads per node, each covers 8 halfs (16 B). fp32 accum.
// ---------------------------------------------------------------------------
template <bool SCALE_SRC>
__device__ __forceinline__ F8 gather_node(int node, int c)
{
    int cnt = g_count[node];
    if (cnt > CAP) cnt = CAP;
    const int* lst = g_csrc + (size_t)node * CAP;

    F8 acc = unpack8(g_msg[(size_t)node * 8 + c]);   // self loop
    if (SCALE_SRC) {
        float dn = g_dinv[node];
        #pragma unroll
        for (int j = 0; j < 8; j++) acc.v[j] *= dn;
    }

    int i = 0;
    for (; i + 4 <= cnt; i += 4) {
        int s0 = __ldg(lst + i);
        int s1 = __ldg(lst + i + 1);
        int s2 = __ldg(lst + i + 2);
        int s3 = __ldg(lst + i + 3);
        F8 a = unpack8(g_msg[(size_t)s0 * 8 + c]);
        F8 b = unpack8(g_msg[(size_t)s1 * 8 + c]);
        F8 cc = unpack8(g_msg[(size_t)s2 * 8 + c]);
        F8 dd = unpack8(g_msg[(size_t)s3 * 8 + c]);
        if (SCALE_SRC) {
            float w0 = g_dinv[s0], w1 = g_dinv[s1];
            float w2 = g_dinv[s2], w3 = g_dinv[s3];
            #pragma unroll
            for (int j = 0; j < 8; j++) {
                acc.v[j] = fmaf(a.v[j], w0, acc.v[j]);
                acc.v[j] = fmaf(b.v[j], w1, acc.v[j]);
                acc.v[j] = fmaf(cc.v[j], w2, acc.v[j]);
                acc.v[j] = fmaf(dd.v[j], w3, acc.v[j]);
            }
        } else {
            #pragma unroll
            for (int j = 0; j < 8; j++)
                acc.v[j] += (a.v[j] + b.v[j]) + (cc.v[j] + dd.v[j]);
        }
    }
    for (; i < cnt; i++) {
        int s0 = __ldg(lst + i);
        F8 a = unpack8(g_msg[(size_t)s0 * 8 + c]);
        if (SCALE_SRC) {
            float w0 = g_dinv[s0];
            #pragma unroll
            for (int j = 0; j < 8; j++) acc.v[j] = fmaf(a.v[j], w0, acc.v[j]);
        } else {
            #pragma unroll
            for (int j = 0; j < 8; j++) acc.v[j] += a.v[j];
        }
    }
    return acc;
}

// ---------------------------------------------------------------------------
// Tensor-core GEMM: 128-row tile, 256 threads (8 warps), warp w = 16 rows.
// Prologue: x' = dinv*relu(agg*dinv+b) (internal) or raw ext (layer 1).
// MMA fp16 -> fp32. Epilogue: half fragments -> smem (xs reuse) -> coalesced
// uint4 global writes. smem = 27.6 KB, 6 blocks/SM.
// ---------------------------------------------------------------------------
static constexpr int XLD = 72;   // fp16 leading dim (mult of 8)

__global__ void __launch_bounds__(256, 6)
k_gemm(const float* __restrict__ xin_ext,   // non-null for layer 1
       int in_buf,                          // fp16 agg buffer (internal)
       const float* __restrict__ W,
       const float* __restrict__ b_prev,    // prev-layer bias (internal)
       int N)
{
    __shared__ __align__(16) __half xs[128 * XLD];   // x tile, then C staging
    __shared__ __align__(16) __half Ws[64 * XLD];

    const int tid  = threadIdx.x;
    const int wid  = tid >> 5;
    const int row0 = blockIdx.x * 128;

    // Load + convert W: 1024 float4, 4 per thread.
    {
        const float4* W4 = (const float4*)W;
        #pragma unroll
        for (int i = 0; i < 4; i++) {
            int j   = tid + i * 256;        // float4 index 0..1023
            int row = j >> 4;               // W row (k)
            int c4  = j & 15;               // float4 col group
            float4 v = W4[j];
            __half2 h0 = __floats2half2_rn(v.x, v.y);
            __half2 h1 = __floats2half2_rn(v.z, v.w);
            uint2 u;
            u.x = *reinterpret_cast<uint32_t*>(&h0);
            u.y = *reinterpret_cast<uint32_t*>(&h1);
            *reinterpret_cast<uint2*>(Ws + row * XLD + c4 * 4) = u;
        }
    }

    // Prologue: build fp16 x' tile.
    if (xin_ext) {
        // Layer 1: raw fp32 node_embed (no dinv access: fork-safe).
        #pragma unroll
        for (int it = 0; it < 8; it++) {
            int j   = tid + it * 256;       // 0..2047
            int r   = j >> 4;
            int c4  = j & 15;
            int row = row0 + r;
            float4 v = make_float4(0.f, 0.f, 0.f, 0.f);
            if (row < N)
                v = ((const float4*)xin_ext)[(size_t)row * 16 + c4];
            __half2 h0 = __floats2half2_rn(v.x, v.y);
            __half2 h1 = __floats2half2_rn(v.z, v.w);
            uint2 u;
            u.x = *reinterpret_cast<uint32_t*>(&h0);
            u.y = *reinterpret_cast<uint32_t*>(&h1);
            *reinterpret_cast<uint2*>(xs + r * XLD + c4 * 4) = u;
        }
    } else {
        // Internal: x' = dinv[row] * relu(agg*dinv[row] + b_prev).
        const uint4* agg4 = in_buf ? g_aggB : g_aggA;
        #pragma unroll
        for (int it = 0; it < 4; it++) {
            int j   = tid + it * 256;       // 0..1023
            int r   = j >> 3;
            int c   = j & 7;                // uint4 group (8 halfs)
            int row = row0 + r;
            F8 o;
            #pragma unroll
            for (int q = 0; q < 8; q++) o.v[q] = 0.f;
            if (row < N) {
                F8 a = unpack8(agg4[(size_t)row * 8 + c]);
                float s  = g_dinv[row];
                float4 b0 = ((const float4*)b_prev)[c * 2];
                float4 b1 = ((const float4*)b_prev)[c * 2 + 1];
                float bb[8] = {b0.x, b0.y, b0.z, b0.w, b1.x, b1.y, b1.z, b1.w};
                #pragma unroll
                for (int q = 0; q < 8; q++)
                    o.v[q] = s * fmaxf(fmaf(a.v[q], s, bb[q]), 0.f);
            }
            *reinterpret_cast<uint4*>(xs + r * XLD + c * 8) = pack8(o);
        }
    }
    __syncthreads();

    // MMA: 4 k-steps x 4 n-tiles of 16x16x16, fp32 accumulate.
    wmma::fragment<wmma::accumulator, 16, 16, 16, float> acc[4];
    #pragma unroll
    for (int n = 0; n < 4; n++) wmma::fill_fragment(acc[n], 0.0f);

    #pragma unroll
    for (int ks = 0; ks < 4; ks++) {
        wmma::fragment<wmma::matrix_a, 16, 16, 16, __half, wmma::row_major> fa;
        wmma::load_matrix_sync(fa, xs + (wid * 16) * XLD + ks * 16, XLD);
        #pragma unroll
        for (int n = 0; n < 4; n++) {
            wmma::fragment<wmma::matrix_b, 16, 16, 16, __half, wmma::row_major> fb;
            wmma::load_matrix_sync(fb, Ws + (ks * 16) * XLD + n * 16, XLD);
            wmma::mma_sync(acc[n], fa, fb, acc[n]);
        }
    }
    __syncthreads();     // x tile dead; xs reused as half C staging

    // Stage: fp32 accum -> fp16 fragment -> smem (ldm = XLD).
    #pragma unroll
    for (int n = 0; n < 4; n++) {
        wmma::fragment<wmma::accumulator, 16, 16, 16, __half> hacc;
        #pragma unroll
        for (int i = 0; i < hacc.num_elements; i++)
            hacc.x[i] = __float2half(acc[n].x[i]);
        wmma::store_matrix_sync(xs + (wid * 16) * XLD + n * 16, hacc, XLD,
                                wmma::mem_row_major);
    }
    __syncthreads();

    // Coalesced global writes: 1024 uint4 (128 rows x 8), 4 per thread.
    #pragma unroll
    for (int it = 0; it < 4; it++) {
        int j   = tid + it * 256;           // 0..1023
        int r   = j >> 3;                   // local row
        int c   = j & 7;                    // uint4 group
        int row = row0 + r;
        if (row < N)
            g_msg[(size_t)row * 8 + c] =
                *reinterpret_cast<const uint4*>(xs + r * XLD + c * 8);
    }
}

// ---------------------------------------------------------------------------
// Gather kernels: 8 threads per node; agg stored fp16.
// ---------------------------------------------------------------------------
template <bool SCALE_SRC>
__global__ void __launch_bounds__(256)
k_gather(int out_buf, int N)
{
    int t = blockIdx.x * blockDim.x + threadIdx.x;
    if (t >= N * 8) return;
    int node = t >> 3;
    int c    = t & 7;
    F8 acc = gather_node<SCALE_SRC>(node, c);
    uint4* agg = out_buf ? g_aggB : g_aggA;
    agg[(size_t)node * 8 + c] = pack8(acc);
}

// Final: out = gather(msg)*dinv + b3  (fp32 out; msg already row-scaled)
__global__ void __launch_bounds__(256)
k_out(float* __restrict__ out, const float* __restrict__ b3, int N)
{
    int t = blockIdx.x * blockDim.x + threadIdx.x;
    if (t >= N * 8) return;
    int node = t >> 3;
    int c    = t & 7;
    F8 acc = gather_node<false>(node, c);
    float s = g_dinv[node];
    float4 b0 = ((const float4*)b3)[c * 2];
    float4 b1 = ((const float4*)b3)[c * 2 + 1];
    float4 o0 = make_float4(fmaf(acc.v[0], s, b0.x), fmaf(acc.v[1], s, b0.y),
                            fmaf(acc.v[2], s, b0.z), fmaf(acc.v[3], s, b0.w));
    float4 o1 = make_float4(fmaf(acc.v[4], s, b1.x), fmaf(acc.v[5], s, b1.y),
                            fmaf(acc.v[6], s, b1.z), fmaf(acc.v[7], s, b1.w));
    float4* dst = (float4*)(out + (size_t)node * 64 + c * 8);
    dst[0] = o0;
    dst[1] = o1;
}

// ---------------------------------------------------------------------------
// Launch. Stream/events created per call (host objects only, no device mem).
// ---------------------------------------------------------------------------
extern "C" void kernel_launch(void* const* d_in, const int* in_sizes, int n_in,
                              void* d_out, int out_size)
{
    const float* node_embed = (const float*)d_in[0];
    const int*   edges      = (const int*)d_in[1];
    const float* W1 = (const float*)d_in[2];
    const float* b1 = (const float*)d_in[3];
    const float* W2 = (const float*)d_in[4];
    const float* b2 = (const float*)d_in[5];
    const float* W3 = (const float*)d_in[6];
    const float* b3 = (const float*)d_in[7];
    float* out = (float*)d_out;

    const int N = in_sizes[0] / D;
    const int E = in_sizes[1] / 2;
    const int* src = edges;
    const int* dst = edges + E;

    const int TB = 256;
    const int gemm_blocks   = (N + 127) / 128;
    const int gather_blocks = (N * 8 + TB - 1) / TB;

    cudaStream_t s2 = nullptr;
    cudaEvent_t evFork = nullptr, evJoin = nullptr;
    bool fork_ok =
        cudaStreamCreateWithFlags(&s2, cudaStreamNonBlocking) == cudaSuccess &&
        cudaEventCreateWithFlags(&evFork, cudaEventDisableTiming) == cudaSuccess &&
        cudaEventCreateWithFlags(&evJoin, cudaEventDisableTiming) == cudaSuccess;

    if (fork_ok) {
        // Fork: CSR build (count/csrc/dinv) || layer-1 GEMM (msg only).
        cudaEventRecord(evFork, 0);
        cudaStreamWaitEvent(s2, evFork, 0);

        k_zero<<<(N + TB - 1) / TB, TB>>>(N);
        k_fill<<<(E + TB - 1) / TB, TB>>>(src, dst, E);
        k_dinv<<<(N + TB - 1) / TB, TB>>>(N);

        k_gemm<<<gemm_blocks, TB, 0, s2>>>(node_embed, 0, W1, nullptr, N);

        cudaEventRecord(evJoin, s2);
        cudaStreamWaitEvent(0, evJoin, 0);
    } else {
        k_zero<<<(N + TB - 1) / TB, TB>>>(N);
        k_fill<<<(E + TB - 1) / TB, TB>>>(src, dst, E);
        k_dinv<<<(N + TB - 1) / TB, TB>>>(N);
        k_gemm<<<gemm_blocks, TB>>>(node_embed, 0, W1, nullptr, N);
    }

    // Layer 1 aggregate (applies dinv[src]) -> A (fp16)
    k_gather<true><<<gather_blocks, TB>>>(0, N);

    // Layer 2: x' = dinv*relu(A*dinv + b1) -> msg; gather -> B (fp16)
    k_gemm<<<gemm_blocks, TB>>>(nullptr, 0, W2, b1, N);
    k_gather<false><<<gather_blocks, TB>>>(1, N);

    // Layer 3: x' = dinv*relu(B*dinv + b2) -> msg; fused gather -> out
    k_gemm<<<gemm_blocks, TB>>>(nullptr, 1, W3, b2, N);
    k_out<<<gather_blocks, TB>>>(out, b3, N);

    // s2/events intentionally not destroyed (unsafe mid-capture; host-only).
}